// round 6
// baseline (speedup 1.0000x reference)
#include <cuda_runtime.h>
#include <math.h>
#include <stdint.h>
#include <stddef.h>

#define NN 50000
#define EE 800000
#define FF 128
#define HBITS 21
#define HSIZE (1u<<HBITS)
#define HMASK (HSIZE-1u)
#define NEGINF __int_as_float(0xff800000)

// ---------------- device scratch ----------------
__device__ float    g_z1[(size_t)NN*FF];
__device__ float    g_p2[(size_t)NN*FF];
__device__ float    g_feat[(size_t)NN*FF];
__device__ float    g_xp1[(size_t)NN*FF];
__device__ float    g_xp2[(size_t)NN*FF];
__device__ float    g_dinv1[NN],  g_dinv2[NN];
__device__ float    g_dcinv1[NN], g_dcinv2[NN];
__device__ float    g_m[NN];
__device__ int      g_pt1[NN], g_pt2[NN];
__device__ int      g_c1[NN], g_c2[NN];
__device__ float    g_cut[EE];
__device__ int      g_s2[EE];
__device__ int      g_d2[EE];
__device__ float    g_w2[EE];
__device__ unsigned g_hash[HSIZE];
__device__ int      g_live[NN];
__device__ int      g_nlive[1];
// CSR (double buffered)
__device__ int      g_rp1[NN+1], g_rp2[NN+1];
__device__ int      g_cnt1[NN],  g_cnt2[NN];
__device__ int      g_col1[EE],  g_col2[EE];
__device__ float    g_val1[EE],  g_val2[EE];

__device__ __forceinline__ float eluf(float v){ return v > 0.f ? v : expm1f(v); }

// ---------------- CSR build ----------------
__global__ void k_count(const int* __restrict__ dst, const float* __restrict__ w,
                        int* __restrict__ cnt){
    int e = blockIdx.x*blockDim.x + threadIdx.x;
    if (e < EE && w[e] > 0.f) atomicAdd(&cnt[dst[e]], 1);
}

// single-block fused scan: rp = exclusive prefix of cnt; also dcinv, m, pt init
__global__ void __launch_bounds__(1024) k_scan_one(const int* __restrict__ cnt,
                                                   float* __restrict__ dcinv,
                                                   int* __restrict__ rp,
                                                   int* __restrict__ pt){
    __shared__ int ssum[1024];
    const int CH = 49;                 // 1024*49 = 50176 >= NN
    int t = threadIdx.x;
    int base = t * CH;
    int local = 0;
    for (int k = 0; k < CH; k++){
        int i = base + k;
        if (i < NN) local += cnt[i];
    }
    ssum[t] = local; __syncthreads();
    #pragma unroll
    for (int off = 1; off < 1024; off <<= 1){
        int tv = (t >= off) ? ssum[t-off] : 0;
        __syncthreads();
        ssum[t] += tv;
        __syncthreads();
    }
    int run = ssum[t] - local;         // exclusive prefix of this chunk
    for (int k = 0; k < CH; k++){
        int i = base + k;
        if (i < NN){
            int c = cnt[i];
            rp[i] = run;
            run += c;
            dcinv[i] = c > 0 ? 1.0f/(float)c : 0.f;
            g_m[i] = NEGINF;
            pt[i] = -1;
        }
    }
    if (t == 1023) rp[NN] = run;
}

// CSR fill (raw w) + normalized-cut + per-src max-cut, one pass over E
__global__ void k_fill(const int* __restrict__ src, const int* __restrict__ dst,
                       const float* __restrict__ w,
                       const int* __restrict__ rp, int* __restrict__ cnt,
                       const float* __restrict__ dcinv,
                       int* __restrict__ col, float* __restrict__ val){
    int e = blockIdx.x*blockDim.x + threadIdx.x;
    if (e >= EE) return;
    int s = src[e], d = dst[e];
    float wv = w[e];
    float cut;
    if (wv > 0.f){
        int pos = rp[d] + atomicAdd(&cnt[d], 1);
        col[pos] = s;
        val[pos] = wv;
        cut = wv * (dcinv[s] + dcinv[d]);
        atomicMax(reinterpret_cast<int*>(&g_m[s]), __float_as_int(cut));
    } else {
        cut = NEGINF;
    }
    g_cut[e] = cut;
}
__global__ void __launch_bounds__(256) k_rowsum(const int* __restrict__ rp,
                                                const float* __restrict__ val,
                                                float* __restrict__ dinv){
    int node = (blockIdx.x*blockDim.x + threadIdx.x) >> 5;
    int l = threadIdx.x & 31;
    if (node >= NN) return;
    int beg = rp[node], end = rp[node+1];
    float sum = 0.f;
    for (int e = beg + l; e < end; e += 32) sum += val[e];
    #pragma unroll
    for (int off = 16; off > 0; off >>= 1) sum += __shfl_xor_sync(0xFFFFFFFFu, sum, off);
    if (l == 0) dinv[node] = sum > 0.f ? rsqrtf(sum) : 0.f;
}

// ---------------- prop: gather, warp per node, 4-way ILP, on-the-fly normalization ----------------
__global__ void __launch_bounds__(256) k_prop(const int* __restrict__ rp,
                                              const int* __restrict__ col,
                                              const float* __restrict__ val,
                                              const float* __restrict__ dinv,
                                              const float* __restrict__ zin,
                                              float* __restrict__ zout){
    int node = (blockIdx.x*blockDim.x + threadIdx.x) >> 5;
    int l = threadIdx.x & 31;
    if (node >= NN) return;
    int beg = rp[node], end = rp[node+1];
    float dn = -__ldg(&dinv[node]);
    const float4* z4 = reinterpret_cast<const float4*>(zin);
    float4 a0 = make_float4(0.f,0.f,0.f,0.f);
    float4 a1 = a0, a2 = a0, a3 = a0;
    int e = beg;
    for (; e + 4 <= end; e += 4){
        int   s0 = __ldg(&col[e  ]), s1 = __ldg(&col[e+1]);
        int   s2 = __ldg(&col[e+2]), s3 = __ldg(&col[e+3]);
        float c0 = __ldg(&val[e  ]) * __ldg(&dinv[s0]);
        float c1 = __ldg(&val[e+1]) * __ldg(&dinv[s1]);
        float c2 = __ldg(&val[e+2]) * __ldg(&dinv[s2]);
        float c3 = __ldg(&val[e+3]) * __ldg(&dinv[s3]);
        float4 v0 = z4[(size_t)s0*(FF/4) + l];
        float4 v1 = z4[(size_t)s1*(FF/4) + l];
        float4 v2 = z4[(size_t)s2*(FF/4) + l];
        float4 v3 = z4[(size_t)s3*(FF/4) + l];
        a0.x = fmaf(c0,v0.x,a0.x); a0.y = fmaf(c0,v0.y,a0.y);
        a0.z = fmaf(c0,v0.z,a0.z); a0.w = fmaf(c0,v0.w,a0.w);
        a1.x = fmaf(c1,v1.x,a1.x); a1.y = fmaf(c1,v1.y,a1.y);
        a1.z = fmaf(c1,v1.z,a1.z); a1.w = fmaf(c1,v1.w,a1.w);
        a2.x = fmaf(c2,v2.x,a2.x); a2.y = fmaf(c2,v2.y,a2.y);
        a2.z = fmaf(c2,v2.z,a2.z); a2.w = fmaf(c2,v2.w,a2.w);
        a3.x = fmaf(c3,v3.x,a3.x); a3.y = fmaf(c3,v3.y,a3.y);
        a3.z = fmaf(c3,v3.z,a3.z); a3.w = fmaf(c3,v3.w,a3.w);
    }
    for (; e < end; e++){
        int   s0 = __ldg(&col[e]);
        float c0 = __ldg(&val[e]) * __ldg(&dinv[s0]);
        float4 v0 = z4[(size_t)s0*(FF/4) + l];
        a0.x = fmaf(c0,v0.x,a0.x); a0.y = fmaf(c0,v0.y,a0.y);
        a0.z = fmaf(c0,v0.z,a0.z); a0.w = fmaf(c0,v0.w,a0.w);
    }
    float4 acc;
    acc.x = dn*((a0.x+a1.x)+(a2.x+a3.x));
    acc.y = dn*((a0.y+a1.y)+(a2.y+a3.y));
    acc.z = dn*((a0.z+a1.z)+(a2.z+a3.z));
    acc.w = dn*((a0.w+a1.w)+(a2.w+a3.w));
    reinterpret_cast<float4*>(zout)[(size_t)node*(FF/4) + l] = acc;
}

// ---------------- fused cheb GEMM + bias + ELU (optional live-row gather) ----------------
#define MT 64
#define KC 32
#define LDZ 68
__global__ void __launch_bounds__(256) k_gemm_elu(const float* __restrict__ z0,
                                                  const float* __restrict__ z1,
                                                  const float* __restrict__ p2,
                                                  const float* __restrict__ Wm,
                                                  const float* __restrict__ bv,
                                                  float* __restrict__ out,
                                                  const int* __restrict__ live,
                                                  const int* __restrict__ nlivep){
    __shared__ float sZ[KC*LDZ];
    __shared__ float sW[KC*FF];
    int tid = threadIdx.x;
    int row0 = blockIdx.x * MT;
    int nrows = live ? __ldg(nlivep) : NN;
    if (row0 >= nrows) return;
    int cg = tid & 31, rg = tid >> 5;
    float acc[8][4];
    #pragma unroll
    for (int r=0;r<8;r++){ acc[r][0]=0.f; acc[r][1]=0.f; acc[r][2]=0.f; acc[r][3]=0.f; }

    const float4* W4 = reinterpret_cast<const float4*>(Wm);
    for (int ch = 0; ch < 12; ch++){
        int part = ch >> 2;
        int kloc = (ch & 3) * KC;
        const float* zsrc = (part==0) ? z0 : (part==1 ? z1 : p2);
        __syncthreads();
        #pragma unroll
        for (int q=0;q<2;q++){
            int i   = tid + 256*q;
            int row = i >> 3;
            int seg = i & 7;
            int idx = row0 + row;
            int grow = (idx < nrows) ? (live ? __ldg(&live[idx]) : idx) : -1;
            float4 v = make_float4(0.f,0.f,0.f,0.f);
            if (grow >= 0){
                v = *reinterpret_cast<const float4*>(zsrc + (size_t)grow*FF + kloc + seg*4);
                if (part == 2){
                    float4 a = *reinterpret_cast<const float4*>(z0 + (size_t)grow*FF + kloc + seg*4);
                    v.x = 2.f*v.x - a.x; v.y = 2.f*v.y - a.y;
                    v.z = 2.f*v.z - a.z; v.w = 2.f*v.w - a.w;
                }
            }
            int kk = seg*4;
            sZ[(kk+0)*LDZ+row] = v.x; sZ[(kk+1)*LDZ+row] = v.y;
            sZ[(kk+2)*LDZ+row] = v.z; sZ[(kk+3)*LDZ+row] = v.w;
        }
        size_t wbase = (size_t)(part*128 + kloc) * (FF/4);
        #pragma unroll
        for (int q=0;q<4;q++){
            int i = tid + 256*q;
            reinterpret_cast<float4*>(sW)[i] = W4[wbase + i];
        }
        __syncthreads();
        #pragma unroll
        for (int kk=0; kk<KC; kk++){
            float4 w4 = *reinterpret_cast<const float4*>(sW + kk*FF + cg*4);
            const float* zr = sZ + kk*LDZ + rg*8;
            float4 za = *reinterpret_cast<const float4*>(zr);
            float4 zb = *reinterpret_cast<const float4*>(zr+4);
            float zv[8] = {za.x,za.y,za.z,za.w,zb.x,zb.y,zb.z,zb.w};
            #pragma unroll
            for (int r=0;r<8;r++){
                acc[r][0] = fmaf(zv[r], w4.x, acc[r][0]);
                acc[r][1] = fmaf(zv[r], w4.y, acc[r][1]);
                acc[r][2] = fmaf(zv[r], w4.z, acc[r][2]);
                acc[r][3] = fmaf(zv[r], w4.w, acc[r][3]);
            }
        }
    }
    float4 b4 = *reinterpret_cast<const float4*>(bv + cg*4);
    #pragma unroll
    for (int r=0;r<8;r++){
        int idx = row0 + rg*8 + r;
        if (idx < nrows){
            int grow = live ? __ldg(&live[idx]) : idx;
            float4 o;
            o.x = eluf(acc[r][0] + b4.x);
            o.y = eluf(acc[r][1] + b4.y);
            o.z = eluf(acc[r][2] + b4.z);
            o.w = eluf(acc[r][3] + b4.w);
            *reinterpret_cast<float4*>(out + (size_t)grow*FF + cg*4) = o;
        }
    }
}

// ---------------- graclus matching ----------------
__global__ void k_partner(const int* __restrict__ src, const int* __restrict__ dst,
                          int* __restrict__ pt){
    int e = blockIdx.x*blockDim.x + threadIdx.x;
    if (e >= EE) return;
    float c = g_cut[e];
    int s = src[e];
    if (c > NEGINF && c == g_m[s])
        atomicMax(&pt[s], dst[e]);
}
__global__ void k_cluster(const int* __restrict__ pt, int* __restrict__ cl){
    int i = blockIdx.x*blockDim.x + threadIdx.x;
    if (i >= NN) return;
    int p = pt[i];
    int c = i;
    if (p >= 0 && p != i && pt[p] == i) c = min(i, p);
    cl[i] = c;
}
// live rows = rows whose pooled feature is nonzero (reps + singletons)
__global__ void k_livelist(const int* __restrict__ pt){
    int i = blockIdx.x*blockDim.x + threadIdx.x;
    if (i >= NN) return;
    int p = pt[i];
    bool dead = (p >= 0 && p != i && pt[p] == i && p < i);
    if (!dead){
        int pos = atomicAdd(&g_nlive[0], 1);
        g_live[pos] = i;
    }
}

// ---------------- pool_x ----------------
__global__ void k_pool(const int* __restrict__ pt,
                       const float* __restrict__ x, float* __restrict__ xp){
    int t = blockIdx.x*blockDim.x + threadIdx.x;
    int j = t >> 5, l = t & 31;
    if (j >= NN) return;
    int p = pt[j];
    bool mut = (p >= 0 && p != j && pt[p] == j);
    float4 o;
    if (mut && p < j){
        o = make_float4(0.f,0.f,0.f,0.f);
    } else {
        float4 a = reinterpret_cast<const float4*>(x + (size_t)j*FF)[l];
        if (mut){
            float4 b = reinterpret_cast<const float4*>(x + (size_t)p*FF)[l];
            a.x = fmaxf(a.x,b.x); a.y = fmaxf(a.y,b.y);
            a.z = fmaxf(a.z,b.z); a.w = fmaxf(a.w,b.w);
        }
        o = a;
    }
    reinterpret_cast<float4*>(xp + (size_t)j*FF)[l] = o;
}

// ---------------- pooled edges ----------------
__global__ void k_pool_edges(const int* __restrict__ src, const int* __restrict__ dst){
    int e = blockIdx.x*blockDim.x + threadIdx.x;
    if (e >= EE) return;
    int s = g_c1[src[e]], d = g_c1[dst[e]];
    g_s2[e] = s; g_d2[e] = d;
    float w = 0.f;
    if (s != d){
        unsigned key = (unsigned)s * (unsigned)NN + (unsigned)d;
        unsigned h = (key * 2654435761u) >> (32 - HBITS);
        h &= HMASK;
        while (true){
            unsigned old = atomicCAS(&g_hash[h], 0xFFFFFFFFu, key);
            if (old == 0xFFFFFFFFu){ w = 1.f; break; }
            if (old == key){ w = 0.f; break; }
            h = (h + 1u) & HMASK;
        }
    }
    g_w2[e] = w;
}

// ---------------- fused log_softmax + gather ----------------
__global__ void k_smax_gather(float* __restrict__ outp){
    int t = blockIdx.x*blockDim.x + threadIdx.x;
    int i = t >> 5, l = t & 31;
    if (i >= NN) return;
    int r = g_c2[g_c1[i]];
    float4 v = reinterpret_cast<const float4*>(g_xp2 + (size_t)r*FF)[l];
    float mx = fmaxf(fmaxf(v.x,v.y), fmaxf(v.z,v.w));
    #pragma unroll
    for (int off=16; off>0; off>>=1) mx = fmaxf(mx, __shfl_xor_sync(0xFFFFFFFFu, mx, off));
    float s = expf(v.x-mx)+expf(v.y-mx)+expf(v.z-mx)+expf(v.w-mx);
    #pragma unroll
    for (int off=16; off>0; off>>=1) s += __shfl_xor_sync(0xFFFFFFFFu, s, off);
    float lse = mx + logf(s);
    v.x -= lse; v.y -= lse; v.z -= lse; v.w -= lse;
    reinterpret_cast<float4*>(outp + (size_t)i*FF)[l] = v;
}

// ---------------- host ----------------
static void* symaddr(const void* s){ void* p = nullptr; cudaGetSymbolAddress(&p, s); return p; }

extern "C" void kernel_launch(void* const* d_in, const int* in_sizes, int n_in,
                              void* d_out, int out_size) {
    const float* x  = (const float*)d_in[0];
    const float* ew = (const float*)d_in[1];
    const float* W1 = (const float*)d_in[2];
    const float* b1 = (const float*)d_in[3];
    const float* W2 = (const float*)d_in[4];
    const float* b2 = (const float*)d_in[5];
    const int*   ei = (const int*)  d_in[6];
    const int* src = ei;
    const int* dst = ei + EE;
    float* outp = (float*)d_out;

    float* z1   = (float*) symaddr(g_z1);
    float* p2   = (float*) symaddr(g_p2);
    float* feat = (float*) symaddr(g_feat);
    float* xp1  = (float*) symaddr(g_xp1);
    float* xp2  = (float*) symaddr(g_xp2);
    int*   cnt1 = (int*)   symaddr(g_cnt1);
    int*   cnt2 = (int*)   symaddr(g_cnt2);
    void*  hash = symaddr(g_hash);
    int*   c1   = (int*)   symaddr(g_c1);
    int*   c2   = (int*)   symaddr(g_c2);
    int*   s2   = (int*)   symaddr(g_s2);
    int*   d2   = (int*)   symaddr(g_d2);
    float* w2   = (float*) symaddr(g_w2);
    int*   rp1  = (int*)   symaddr(g_rp1);
    int*   rp2  = (int*)   symaddr(g_rp2);
    int*   col1 = (int*)   symaddr(g_col1);
    int*   col2 = (int*)   symaddr(g_col2);
    float* val1 = (float*) symaddr(g_val1);
    float* val2 = (float*) symaddr(g_val2);
    float* di1  = (float*) symaddr(g_dinv1);
    float* di2  = (float*) symaddr(g_dinv2);
    float* dc1  = (float*) symaddr(g_dcinv1);
    float* dc2  = (float*) symaddr(g_dcinv2);
    int*   pt1  = (int*)   symaddr(g_pt1);
    int*   pt2  = (int*)   symaddr(g_pt2);
    int*   live = (int*)   symaddr(g_live);
    int*   nliv = (int*)   symaddr(g_nlive);

    static cudaStream_t sB = nullptr;
    static cudaEvent_t evFill, evC1, evB2;
    if (!sB){
        cudaStreamCreate(&sB);
        cudaEventCreateWithFlags(&evFill, cudaEventDisableTiming);
        cudaEventCreateWithFlags(&evC1,  cudaEventDisableTiming);
        cudaEventCreateWithFlags(&evB2,  cudaEventDisableTiming);
    }

    const int EB = EE/256;
    const int NB = (NN+255)/256;
    const int PB = (NN*32+255)/256;
    const int GB = (NN+MT-1)/MT;

    // ===== A: block-1 CSR build =====
    cudaMemsetAsync(cnt1, 0, NN*sizeof(int));
    k_count<<<EB,256>>>(dst, ew, cnt1);
    k_scan_one<<<1,1024>>>(cnt1, dc1, rp1, pt1);
    cudaMemsetAsync(cnt1, 0, NN*sizeof(int));
    k_fill<<<EB,256>>>(src, dst, ew, rp1, cnt1, dc1, col1, val1);
    cudaEventRecord(evFill, 0);

    // ===== B: matching + pooled-graph CSR build (hidden) =====
    cudaStreamWaitEvent(sB, evFill, 0);
    k_partner<<<EB,256,0,sB>>>(src, dst, pt1);
    k_cluster<<<NB,256,0,sB>>>(pt1, c1);
    cudaEventRecord(evC1, sB);
    cudaMemsetAsync(nliv, 0, sizeof(int), sB);
    k_livelist<<<NB,256,0,sB>>>(pt1);
    cudaMemsetAsync(hash, 0xFF, HSIZE*sizeof(unsigned), sB);
    k_pool_edges<<<EB,256,0,sB>>>(src, dst);
    cudaMemsetAsync(cnt2, 0, NN*sizeof(int), sB);
    k_count<<<EB,256,0,sB>>>(d2, w2, cnt2);
    k_scan_one<<<1,1024,0,sB>>>(cnt2, dc2, rp2, pt2);
    cudaMemsetAsync(cnt2, 0, NN*sizeof(int), sB);
    k_fill<<<EB,256,0,sB>>>(s2, d2, w2, rp2, cnt2, dc2, col2, val2);
    k_rowsum<<<PB,256,0,sB>>>(rp2, val2, di2);
    k_partner<<<EB,256,0,sB>>>(s2, d2, pt2);
    k_cluster<<<NB,256,0,sB>>>(pt2, c2);
    cudaEventRecord(evB2, sB);

    // ===== A: block-1 heavy chain =====
    k_rowsum<<<PB,256>>>(rp1, val1, di1);
    k_prop<<<PB,256>>>(rp1, col1, val1, di1, x, z1);
    k_prop<<<PB,256>>>(rp1, col1, val1, di1, z1, p2);
    k_gemm_elu<<<GB,256>>>(x, z1, p2, W1, b1, feat, nullptr, nullptr);
    cudaStreamWaitEvent(0, evC1, 0);
    k_pool<<<PB,256>>>(pt1, feat, xp1);

    // ===== A: block-2 heavy chain =====
    cudaStreamWaitEvent(0, evB2, 0);
    k_prop<<<PB,256>>>(rp2, col2, val2, di2, xp1, z1);
    k_prop<<<PB,256>>>(rp2, col2, val2, di2, z1, p2);
    k_gemm_elu<<<GB,256>>>(xp1, z1, p2, W2, b2, feat, live, nliv);
    k_pool<<<PB,256>>>(pt2, feat, xp2);

    // ===== output =====
    k_smax_gather<<<PB,256>>>(outp);
}

// round 7
// speedup vs baseline: 1.3239x; 1.3239x over previous
#include <cuda_runtime.h>
#include <math.h>
#include <stdint.h>
#include <stddef.h>

#define NN 50000
#define EE 800000
#define FF 128
#define HBITS 21
#define HSIZE (1u<<HBITS)
#define HMASK (HSIZE-1u)
#define NEGINF __int_as_float(0xff800000)

// ---------------- device scratch ----------------
__device__ float    g_z1[(size_t)NN*FF];
__device__ float    g_p2[(size_t)NN*FF];
__device__ float    g_feat[(size_t)NN*FF];
__device__ float    g_xp1[(size_t)NN*FF];
__device__ float    g_xp2[(size_t)NN*FF];
__device__ float    g_dinv1[NN],  g_dinv2[NN];
__device__ float    g_dcinv1[NN], g_dcinv2[NN];
__device__ float    g_m[NN];
__device__ int      g_pt1[NN], g_pt2[NN];
__device__ int      g_c1[NN], g_c2[NN];
__device__ float    g_cut[EE];
__device__ int      g_s2[EE];
__device__ int      g_d2[EE];
__device__ float    g_w2[EE];
__device__ unsigned g_hash[HSIZE];
__device__ int      g_live[NN];
__device__ int      g_nlive[1];
// CSR (double buffered)
__device__ int      g_rp1[NN+1], g_rp2[NN+1];
__device__ int      g_cnt1[NN],  g_cnt2[NN];
__device__ int      g_bsum[256];
__device__ int      g_total;
__device__ int      g_col1[EE],  g_col2[EE];
__device__ float    g_val1[EE],  g_val2[EE];

__device__ __forceinline__ float eluf(float v){ return v > 0.f ? v : expm1f(v); }

// ---------------- CSR build ----------------
__global__ void k_count(const int* __restrict__ dst, const float* __restrict__ w,
                        int* __restrict__ cnt){
    int e = blockIdx.x*blockDim.x + threadIdx.x;
    if (e < EE && w[e] > 0.f) atomicAdd(&cnt[dst[e]], 1);
}
__global__ void k_scan1(const int* __restrict__ cnt, float* __restrict__ dcinv,
                        int* __restrict__ rp){
    __shared__ int s[256];
    int t = threadIdx.x;
    int i = blockIdx.x*256 + t;
    int v = (i < NN) ? cnt[i] : 0;
    if (i < NN) dcinv[i] = v > 0 ? 1.0f/(float)v : 0.f;
    s[t] = v; __syncthreads();
    #pragma unroll
    for (int off = 1; off < 256; off <<= 1){
        int tv = (t >= off) ? s[t-off] : 0;
        __syncthreads();
        s[t] += tv;
        __syncthreads();
    }
    if (i < NN) rp[i] = s[t] - v;
    if (t == 255) g_bsum[blockIdx.x] = s[255];
}
__global__ void k_scan2(){
    __shared__ int s[256];
    int t = threadIdx.x;
    int v = (t < 196) ? g_bsum[t] : 0;
    s[t] = v; __syncthreads();
    #pragma unroll
    for (int off = 1; off < 256; off <<= 1){
        int tv = (t >= off) ? s[t-off] : 0;
        __syncthreads();
        s[t] += tv;
        __syncthreads();
    }
    if (t < 196) g_bsum[t] = s[t] - v;
    if (t == 255) g_total = s[255];
}
__global__ void k_scan3(int* __restrict__ rp, int* __restrict__ pt){
    int i = blockIdx.x*256 + threadIdx.x;
    if (i < NN){
        rp[i] += g_bsum[blockIdx.x];
        g_m[i] = NEGINF;
        pt[i] = -1;
    }
    if (i == 0) rp[NN] = g_total;
}
// CSR fill (raw weights) + normalized-cut + per-src max-cut, one pass over E
__global__ void k_fill(const int* __restrict__ src, const int* __restrict__ dst,
                       const float* __restrict__ w,
                       const int* __restrict__ rp, int* __restrict__ cnt,
                       const float* __restrict__ dcinv,
                       int* __restrict__ col, float* __restrict__ val){
    int e = blockIdx.x*blockDim.x + threadIdx.x;
    if (e >= EE) return;
    int s = src[e], d = dst[e];
    float wv = w[e];
    float cut;
    if (wv > 0.f){
        int pos = rp[d] + atomicAdd(&cnt[d], 1);
        col[pos] = s;
        val[pos] = wv;
        cut = wv * (dcinv[s] + dcinv[d]);
        atomicMax(reinterpret_cast<int*>(&g_m[s]), __float_as_int(cut));
    } else {
        cut = NEGINF;
    }
    g_cut[e] = cut;
}
__global__ void __launch_bounds__(256) k_rowsum(const int* __restrict__ rp,
                                                const float* __restrict__ val,
                                                float* __restrict__ dinv){
    int node = (blockIdx.x*blockDim.x + threadIdx.x) >> 5;
    int l = threadIdx.x & 31;
    if (node >= NN) return;
    int beg = rp[node], end = rp[node+1];
    float sum = 0.f;
    for (int e = beg + l; e < end; e += 32) sum += val[e];
    #pragma unroll
    for (int off = 16; off > 0; off >>= 1) sum += __shfl_xor_sync(0xFFFFFFFFu, sum, off);
    if (l == 0) dinv[node] = sum > 0.f ? rsqrtf(sum) : 0.f;
}
// fold -dinv[d]*dinv[s] into CSR values (off critical path cost, keeps prop lean)
__global__ void __launch_bounds__(256) k_norm(const int* __restrict__ rp,
                                              const int* __restrict__ col,
                                              float* __restrict__ val,
                                              const float* __restrict__ dinv){
    int node = (blockIdx.x*blockDim.x + threadIdx.x) >> 5;
    int l = threadIdx.x & 31;
    if (node >= NN) return;
    int beg = rp[node], end = rp[node+1];
    float di = -dinv[node];
    for (int e = beg + l; e < end; e += 32)
        val[e] = di * dinv[col[e]] * val[e];
}

// ---------------- prop: pure gather, warp per node, 4-way ILP ----------------
__global__ void __launch_bounds__(256) k_prop(const int* __restrict__ rp,
                                              const int* __restrict__ col,
                                              const float* __restrict__ val,
                                              const float* __restrict__ zin,
                                              float* __restrict__ zout){
    int node = (blockIdx.x*blockDim.x + threadIdx.x) >> 5;
    int l = threadIdx.x & 31;
    if (node >= NN) return;
    int beg = rp[node], end = rp[node+1];
    const float4* z4 = reinterpret_cast<const float4*>(zin);
    float4 a0 = make_float4(0.f,0.f,0.f,0.f);
    float4 a1 = a0, a2 = a0, a3 = a0;
    int e = beg;
    for (; e + 4 <= end; e += 4){
        int   s0 = __ldg(&col[e  ]), s1 = __ldg(&col[e+1]);
        int   s2 = __ldg(&col[e+2]), s3 = __ldg(&col[e+3]);
        float c0 = __ldg(&val[e  ]), c1 = __ldg(&val[e+1]);
        float c2 = __ldg(&val[e+2]), c3 = __ldg(&val[e+3]);
        float4 v0 = z4[(size_t)s0*(FF/4) + l];
        float4 v1 = z4[(size_t)s1*(FF/4) + l];
        float4 v2 = z4[(size_t)s2*(FF/4) + l];
        float4 v3 = z4[(size_t)s3*(FF/4) + l];
        a0.x = fmaf(c0,v0.x,a0.x); a0.y = fmaf(c0,v0.y,a0.y);
        a0.z = fmaf(c0,v0.z,a0.z); a0.w = fmaf(c0,v0.w,a0.w);
        a1.x = fmaf(c1,v1.x,a1.x); a1.y = fmaf(c1,v1.y,a1.y);
        a1.z = fmaf(c1,v1.z,a1.z); a1.w = fmaf(c1,v1.w,a1.w);
        a2.x = fmaf(c2,v2.x,a2.x); a2.y = fmaf(c2,v2.y,a2.y);
        a2.z = fmaf(c2,v2.z,a2.z); a2.w = fmaf(c2,v2.w,a2.w);
        a3.x = fmaf(c3,v3.x,a3.x); a3.y = fmaf(c3,v3.y,a3.y);
        a3.z = fmaf(c3,v3.z,a3.z); a3.w = fmaf(c3,v3.w,a3.w);
    }
    for (; e < end; e++){
        int   s0 = __ldg(&col[e]);
        float c0 = __ldg(&val[e]);
        float4 v0 = z4[(size_t)s0*(FF/4) + l];
        a0.x = fmaf(c0,v0.x,a0.x); a0.y = fmaf(c0,v0.y,a0.y);
        a0.z = fmaf(c0,v0.z,a0.z); a0.w = fmaf(c0,v0.w,a0.w);
    }
    float4 acc;
    acc.x = (a0.x+a1.x)+(a2.x+a3.x);
    acc.y = (a0.y+a1.y)+(a2.y+a3.y);
    acc.z = (a0.z+a1.z)+(a2.z+a3.z);
    acc.w = (a0.w+a1.w)+(a2.w+a3.w);
    reinterpret_cast<float4*>(zout)[(size_t)node*(FF/4) + l] = acc;
}

// ---------------- fused cheb GEMM + bias + ELU (optional live-row gather) ----------------
#define MT 64
#define KC 32
#define LDZ 68
__global__ void __launch_bounds__(256) k_gemm_elu(const float* __restrict__ z0,
                                                  const float* __restrict__ z1,
                                                  const float* __restrict__ p2,
                                                  const float* __restrict__ Wm,
                                                  const float* __restrict__ bv,
                                                  float* __restrict__ out,
                                                  const int* __restrict__ live,
                                                  const int* __restrict__ nlivep){
    __shared__ float sZ[KC*LDZ];
    __shared__ float sW[KC*FF];
    int tid = threadIdx.x;
    int row0 = blockIdx.x * MT;
    int nrows = live ? __ldg(nlivep) : NN;
    if (row0 >= nrows) return;
    int cg = tid & 31, rg = tid >> 5;
    float acc[8][4];
    #pragma unroll
    for (int r=0;r<8;r++){ acc[r][0]=0.f; acc[r][1]=0.f; acc[r][2]=0.f; acc[r][3]=0.f; }

    const float4* W4 = reinterpret_cast<const float4*>(Wm);
    for (int ch = 0; ch < 12; ch++){
        int part = ch >> 2;
        int kloc = (ch & 3) * KC;
        const float* zsrc = (part==0) ? z0 : (part==1 ? z1 : p2);
        __syncthreads();
        #pragma unroll
        for (int q=0;q<2;q++){
            int i   = tid + 256*q;
            int row = i >> 3;
            int seg = i & 7;
            int idx = row0 + row;
            int grow = (idx < nrows) ? (live ? __ldg(&live[idx]) : idx) : -1;
            float4 v = make_float4(0.f,0.f,0.f,0.f);
            if (grow >= 0){
                v = *reinterpret_cast<const float4*>(zsrc + (size_t)grow*FF + kloc + seg*4);
                if (part == 2){
                    float4 a = *reinterpret_cast<const float4*>(z0 + (size_t)grow*FF + kloc + seg*4);
                    v.x = 2.f*v.x - a.x; v.y = 2.f*v.y - a.y;
                    v.z = 2.f*v.z - a.z; v.w = 2.f*v.w - a.w;
                }
            }
            int kk = seg*4;
            sZ[(kk+0)*LDZ+row] = v.x; sZ[(kk+1)*LDZ+row] = v.y;
            sZ[(kk+2)*LDZ+row] = v.z; sZ[(kk+3)*LDZ+row] = v.w;
        }
        size_t wbase = (size_t)(part*128 + kloc) * (FF/4);
        #pragma unroll
        for (int q=0;q<4;q++){
            int i = tid + 256*q;
            reinterpret_cast<float4*>(sW)[i] = W4[wbase + i];
        }
        __syncthreads();
        #pragma unroll
        for (int kk=0; kk<KC; kk++){
            float4 w4 = *reinterpret_cast<const float4*>(sW + kk*FF + cg*4);
            const float* zr = sZ + kk*LDZ + rg*8;
            float4 za = *reinterpret_cast<const float4*>(zr);
            float4 zb = *reinterpret_cast<const float4*>(zr+4);
            float zv[8] = {za.x,za.y,za.z,za.w,zb.x,zb.y,zb.z,zb.w};
            #pragma unroll
            for (int r=0;r<8;r++){
                acc[r][0] = fmaf(zv[r], w4.x, acc[r][0]);
                acc[r][1] = fmaf(zv[r], w4.y, acc[r][1]);
                acc[r][2] = fmaf(zv[r], w4.z, acc[r][2]);
                acc[r][3] = fmaf(zv[r], w4.w, acc[r][3]);
            }
        }
    }
    float4 b4 = *reinterpret_cast<const float4*>(bv + cg*4);
    #pragma unroll
    for (int r=0;r<8;r++){
        int idx = row0 + rg*8 + r;
        if (idx < nrows){
            int grow = live ? __ldg(&live[idx]) : idx;
            float4 o;
            o.x = eluf(acc[r][0] + b4.x);
            o.y = eluf(acc[r][1] + b4.y);
            o.z = eluf(acc[r][2] + b4.z);
            o.w = eluf(acc[r][3] + b4.w);
            *reinterpret_cast<float4*>(out + (size_t)grow*FF + cg*4) = o;
        }
    }
}

// ---------------- graclus matching ----------------
__global__ void k_partner(const int* __restrict__ src, const int* __restrict__ dst,
                          int* __restrict__ pt){
    int e = blockIdx.x*blockDim.x + threadIdx.x;
    if (e >= EE) return;
    float c = g_cut[e];
    int s = src[e];
    if (c > NEGINF && c == g_m[s])
        atomicMax(&pt[s], dst[e]);
}
__global__ void k_cluster(const int* __restrict__ pt, int* __restrict__ cl){
    int i = blockIdx.x*blockDim.x + threadIdx.x;
    if (i >= NN) return;
    int p = pt[i];
    int c = i;
    if (p >= 0 && p != i && pt[p] == i) c = min(i, p);
    cl[i] = c;
}
// live rows for gemm2 = rows whose pooled feature is nonzero (reps + singletons)
__global__ void k_livelist(const int* __restrict__ pt){
    int i = blockIdx.x*blockDim.x + threadIdx.x;
    if (i >= NN) return;
    int p = pt[i];
    bool dead = (p >= 0 && p != i && pt[p] == i && p < i);
    if (!dead){
        int pos = atomicAdd(&g_nlive[0], 1);
        g_live[pos] = i;
    }
}

// ---------------- pool_x (clusters are pairs) ----------------
__global__ void k_pool(const int* __restrict__ pt,
                       const float* __restrict__ x, float* __restrict__ xp){
    int t = blockIdx.x*blockDim.x + threadIdx.x;
    int j = t >> 5, l = t & 31;
    if (j >= NN) return;
    int p = pt[j];
    bool mut = (p >= 0 && p != j && pt[p] == j);
    float4 o;
    if (mut && p < j){
        o = make_float4(0.f,0.f,0.f,0.f);
    } else {
        float4 a = reinterpret_cast<const float4*>(x + (size_t)j*FF)[l];
        if (mut){
            float4 b = reinterpret_cast<const float4*>(x + (size_t)p*FF)[l];
            a.x = fmaxf(a.x,b.x); a.y = fmaxf(a.y,b.y);
            a.z = fmaxf(a.z,b.z); a.w = fmaxf(a.w,b.w);
        }
        o = a;
    }
    reinterpret_cast<float4*>(xp + (size_t)j*FF)[l] = o;
}

// ---------------- pooled edges: relabel + hash dedup ----------------
__global__ void k_pool_edges(const int* __restrict__ src, const int* __restrict__ dst){
    int e = blockIdx.x*blockDim.x + threadIdx.x;
    if (e >= EE) return;
    int s = g_c1[src[e]], d = g_c1[dst[e]];
    g_s2[e] = s; g_d2[e] = d;
    float w = 0.f;
    if (s != d){
        unsigned key = (unsigned)s * (unsigned)NN + (unsigned)d;
        unsigned h = (key * 2654435761u) >> (32 - HBITS);
        h &= HMASK;
        while (true){
            unsigned old = atomicCAS(&g_hash[h], 0xFFFFFFFFu, key);
            if (old == 0xFFFFFFFFu){ w = 1.f; break; }
            if (old == key){ w = 0.f; break; }
            h = (h + 1u) & HMASK;
        }
    }
    g_w2[e] = w;
}

// ---------------- fused log_softmax + gather ----------------
__global__ void k_smax_gather(float* __restrict__ outp){
    int t = blockIdx.x*blockDim.x + threadIdx.x;
    int i = t >> 5, l = t & 31;
    if (i >= NN) return;
    int r = g_c2[g_c1[i]];
    float4 v = reinterpret_cast<const float4*>(g_xp2 + (size_t)r*FF)[l];
    float mx = fmaxf(fmaxf(v.x,v.y), fmaxf(v.z,v.w));
    #pragma unroll
    for (int off=16; off>0; off>>=1) mx = fmaxf(mx, __shfl_xor_sync(0xFFFFFFFFu, mx, off));
    float s = expf(v.x-mx)+expf(v.y-mx)+expf(v.z-mx)+expf(v.w-mx);
    #pragma unroll
    for (int off=16; off>0; off>>=1) s += __shfl_xor_sync(0xFFFFFFFFu, s, off);
    float lse = mx + logf(s);
    v.x -= lse; v.y -= lse; v.z -= lse; v.w -= lse;
    reinterpret_cast<float4*>(outp + (size_t)i*FF)[l] = v;
}

// ---------------- host ----------------
static void* symaddr(const void* s){ void* p = nullptr; cudaGetSymbolAddress(&p, s); return p; }

extern "C" void kernel_launch(void* const* d_in, const int* in_sizes, int n_in,
                              void* d_out, int out_size) {
    const float* x  = (const float*)d_in[0];
    const float* ew = (const float*)d_in[1];
    const float* W1 = (const float*)d_in[2];
    const float* b1 = (const float*)d_in[3];
    const float* W2 = (const float*)d_in[4];
    const float* b2 = (const float*)d_in[5];
    const int*   ei = (const int*)  d_in[6];
    const int* src = ei;
    const int* dst = ei + EE;
    float* outp = (float*)d_out;

    float* z1   = (float*) symaddr(g_z1);
    float* p2   = (float*) symaddr(g_p2);
    float* feat = (float*) symaddr(g_feat);
    float* xp1  = (float*) symaddr(g_xp1);
    float* xp2  = (float*) symaddr(g_xp2);
    int*   cnt1 = (int*)   symaddr(g_cnt1);
    int*   cnt2 = (int*)   symaddr(g_cnt2);
    void*  hash = symaddr(g_hash);
    int*   c1   = (int*)   symaddr(g_c1);
    int*   c2   = (int*)   symaddr(g_c2);
    int*   s2   = (int*)   symaddr(g_s2);
    int*   d2   = (int*)   symaddr(g_d2);
    float* w2   = (float*) symaddr(g_w2);
    int*   rp1  = (int*)   symaddr(g_rp1);
    int*   rp2  = (int*)   symaddr(g_rp2);
    int*   col1 = (int*)   symaddr(g_col1);
    int*   col2 = (int*)   symaddr(g_col2);
    float* val1 = (float*) symaddr(g_val1);
    float* val2 = (float*) symaddr(g_val2);
    float* di1  = (float*) symaddr(g_dinv1);
    float* di2  = (float*) symaddr(g_dinv2);
    float* dc1  = (float*) symaddr(g_dcinv1);
    float* dc2  = (float*) symaddr(g_dcinv2);
    int*   pt1  = (int*)   symaddr(g_pt1);
    int*   pt2  = (int*)   symaddr(g_pt2);
    int*   live = (int*)   symaddr(g_live);
    int*   nliv = (int*)   symaddr(g_nlive);

    static cudaStream_t sB = nullptr;
    static cudaEvent_t evFill, evC1, evB2;
    if (!sB){
        cudaStreamCreate(&sB);
        cudaEventCreateWithFlags(&evFill, cudaEventDisableTiming);
        cudaEventCreateWithFlags(&evC1,  cudaEventDisableTiming);
        cudaEventCreateWithFlags(&evB2,  cudaEventDisableTiming);
    }

    const int EB = EE/256;
    const int NB = (NN+255)/256;
    const int PB = (NN*32+255)/256;
    const int GB = (NN+MT-1)/MT;

    // ===== A: block-1 CSR build =====
    cudaMemsetAsync(cnt1, 0, NN*sizeof(int));
    k_count<<<EB,256>>>(dst, ew, cnt1);
    k_scan1<<<NB,256>>>(cnt1, dc1, rp1);
    k_scan2<<<1,256>>>();
    k_scan3<<<NB,256>>>(rp1, pt1);
    cudaMemsetAsync(cnt1, 0, NN*sizeof(int));
    k_fill<<<EB,256>>>(src, dst, ew, rp1, cnt1, dc1, col1, val1);
    cudaEventRecord(evFill, 0);

    // ===== B: matching + pooled-graph CSR build (hidden) =====
    cudaStreamWaitEvent(sB, evFill, 0);
    k_partner<<<EB,256,0,sB>>>(src, dst, pt1);
    k_cluster<<<NB,256,0,sB>>>(pt1, c1);
    cudaEventRecord(evC1, sB);
    cudaMemsetAsync(nliv, 0, sizeof(int), sB);
    k_livelist<<<NB,256,0,sB>>>(pt1);
    cudaMemsetAsync(hash, 0xFF, HSIZE*sizeof(unsigned), sB);
    k_pool_edges<<<EB,256,0,sB>>>(src, dst);
    cudaMemsetAsync(cnt2, 0, NN*sizeof(int), sB);
    k_count<<<EB,256,0,sB>>>(d2, w2, cnt2);
    k_scan1<<<NB,256,0,sB>>>(cnt2, dc2, rp2);
    k_scan2<<<1,256,0,sB>>>();
    k_scan3<<<NB,256,0,sB>>>(rp2, pt2);
    cudaMemsetAsync(cnt2, 0, NN*sizeof(int), sB);
    k_fill<<<EB,256,0,sB>>>(s2, d2, w2, rp2, cnt2, dc2, col2, val2);
    k_rowsum<<<PB,256,0,sB>>>(rp2, val2, di2);
    k_norm<<<PB,256,0,sB>>>(rp2, col2, val2, di2);
    k_partner<<<EB,256,0,sB>>>(s2, d2, pt2);
    k_cluster<<<NB,256,0,sB>>>(pt2, c2);
    cudaEventRecord(evB2, sB);

    // ===== A: block-1 heavy chain =====
    k_rowsum<<<PB,256>>>(rp1, val1, di1);
    k_norm<<<PB,256>>>(rp1, col1, val1, di1);
    k_prop<<<PB,256>>>(rp1, col1, val1, x, z1);
    k_prop<<<PB,256>>>(rp1, col1, val1, z1, p2);
    k_gemm_elu<<<GB,256>>>(x, z1, p2, W1, b1, feat, nullptr, nullptr);
    cudaStreamWaitEvent(0, evC1, 0);
    k_pool<<<PB,256>>>(pt1, feat, xp1);

    // ===== A: block-2 heavy chain =====
    cudaStreamWaitEvent(0, evB2, 0);
    k_prop<<<PB,256>>>(rp2, col2, val2, xp1, z1);
    k_prop<<<PB,256>>>(rp2, col2, val2, z1, p2);
    k_gemm_elu<<<GB,256>>>(xp1, z1, p2, W2, b2, feat, live, nliv);
    k_pool<<<PB,256>>>(pt2, feat, xp2);

    // ===== output =====
    k_smax_gather<<<PB,256>>>(outp);
}

// round 9
// speedup vs baseline: 1.3446x; 1.0156x over previous
#include <cuda_runtime.h>
#include <cuda_fp16.h>
#include <math.h>
#include <stdint.h>
#include <stddef.h>

#define NN 50000
#define EE 800000
#define FF 128
#define HBITS 21
#define HSIZE (1u<<HBITS)
#define HMASK (HSIZE-1u)
#define NEGINF __int_as_float(0xff800000)

// ---------------- device scratch ----------------
__device__ float    g_z1[(size_t)NN*FF];
__device__ float    g_p2[(size_t)NN*FF];
__device__ float    g_feat[(size_t)NN*FF];
__device__ float    g_xp1[(size_t)NN*FF];
__device__ float    g_xp2[(size_t)NN*FF];
__device__ __half   g_h_in[(size_t)NN*FF];   // fp16 mirror of prop input (x / xp1)
__device__ __half   g_h_z1[(size_t)NN*FF];   // fp16 mirror of z1
__device__ float    g_dinv1[NN],  g_dinv2[NN];
__device__ float    g_dcinv1[NN], g_dcinv2[NN];
__device__ float    g_m[NN];
__device__ int      g_pt1[NN], g_pt2[NN];
__device__ int      g_c1[NN], g_c2[NN];
__device__ float    g_cut[EE];
__device__ int      g_s2[EE];
__device__ int      g_d2[EE];
__device__ float    g_w2[EE];
__device__ unsigned g_hash[HSIZE];
__device__ int      g_live[NN];
__device__ int      g_nlive[1];
// CSR (double buffered)
__device__ int      g_rp1[NN+1], g_rp2[NN+1];
__device__ int      g_cnt1[NN],  g_cnt2[NN];
__device__ int      g_bsum[256];
__device__ int      g_total;
__device__ int      g_col1[EE],  g_col2[EE];
__device__ float    g_val1[EE],  g_val2[EE];

__device__ __forceinline__ float eluf(float v){ return v > 0.f ? v : expm1f(v); }

__device__ __forceinline__ float4 h4_to_f4(uint2 u){
    __half2 h0 = *reinterpret_cast<__half2*>(&u.x);
    __half2 h1 = *reinterpret_cast<__half2*>(&u.y);
    float2 f0 = __half22float2(h0), f1 = __half22float2(h1);
    return make_float4(f0.x, f0.y, f1.x, f1.y);
}
__device__ __forceinline__ uint2 f4_to_h4(float4 v){
    __half2 h0 = __floats2half2_rn(v.x, v.y);
    __half2 h1 = __floats2half2_rn(v.z, v.w);
    uint2 u;
    u.x = *reinterpret_cast<unsigned*>(&h0);
    u.y = *reinterpret_cast<unsigned*>(&h1);
    return u;
}

// ---------------- fp32 -> fp16 mirror convert ----------------
__global__ void k_cvt(const float* __restrict__ in, __half* __restrict__ out){
    int i = blockIdx.x*blockDim.x + threadIdx.x;
    if (i >= NN*FF/4) return;
    float4 v = reinterpret_cast<const float4*>(in)[i];
    reinterpret_cast<uint2*>(out)[i] = f4_to_h4(v);
}

// ---------------- CSR build ----------------
__global__ void k_count(const int* __restrict__ dst, const float* __restrict__ w,
                        int* __restrict__ cnt){
    int e = blockIdx.x*blockDim.x + threadIdx.x;
    if (e < EE && w[e] > 0.f) atomicAdd(&cnt[dst[e]], 1);
}
__global__ void k_scan1(const int* __restrict__ cnt, float* __restrict__ dcinv,
                        int* __restrict__ rp){
    __shared__ int s[256];
    int t = threadIdx.x;
    int i = blockIdx.x*256 + t;
    int v = (i < NN) ? cnt[i] : 0;
    if (i < NN) dcinv[i] = v > 0 ? 1.0f/(float)v : 0.f;
    s[t] = v; __syncthreads();
    #pragma unroll
    for (int off = 1; off < 256; off <<= 1){
        int tv = (t >= off) ? s[t-off] : 0;
        __syncthreads();
        s[t] += tv;
        __syncthreads();
    }
    if (i < NN) rp[i] = s[t] - v;
    if (t == 255) g_bsum[blockIdx.x] = s[255];
}
__global__ void k_scan2(){
    __shared__ int s[256];
    int t = threadIdx.x;
    int v = (t < 196) ? g_bsum[t] : 0;
    s[t] = v; __syncthreads();
    #pragma unroll
    for (int off = 1; off < 256; off <<= 1){
        int tv = (t >= off) ? s[t-off] : 0;
        __syncthreads();
        s[t] += tv;
        __syncthreads();
    }
    if (t < 196) g_bsum[t] = s[t] - v;
    if (t == 255) g_total = s[255];
}
__global__ void k_scan3(int* __restrict__ rp, int* __restrict__ pt){
    int i = blockIdx.x*256 + threadIdx.x;
    if (i < NN){
        rp[i] += g_bsum[blockIdx.x];
        g_m[i] = NEGINF;
        pt[i] = -1;
    }
    if (i == 0) rp[NN] = g_total;
}
__global__ void k_fill(const int* __restrict__ src, const int* __restrict__ dst,
                       const float* __restrict__ w,
                       const int* __restrict__ rp, int* __restrict__ cnt,
                       const float* __restrict__ dcinv,
                       int* __restrict__ col, float* __restrict__ val){
    int e = blockIdx.x*blockDim.x + threadIdx.x;
    if (e >= EE) return;
    int s = src[e], d = dst[e];
    float wv = w[e];
    float cut;
    if (wv > 0.f){
        int pos = rp[d] + atomicAdd(&cnt[d], 1);
        col[pos] = s;
        val[pos] = wv;
        cut = wv * (dcinv[s] + dcinv[d]);
        atomicMax(reinterpret_cast<int*>(&g_m[s]), __float_as_int(cut));
    } else {
        cut = NEGINF;
    }
    g_cut[e] = cut;
}
__global__ void __launch_bounds__(256) k_rowsum(const int* __restrict__ rp,
                                                const float* __restrict__ val,
                                                float* __restrict__ dinv){
    int node = (blockIdx.x*blockDim.x + threadIdx.x) >> 5;
    int l = threadIdx.x & 31;
    if (node >= NN) return;
    int beg = rp[node], end = rp[node+1];
    float sum = 0.f;
    for (int e = beg + l; e < end; e += 32) sum += val[e];
    #pragma unroll
    for (int off = 16; off > 0; off >>= 1) sum += __shfl_xor_sync(0xFFFFFFFFu, sum, off);
    if (l == 0) dinv[node] = sum > 0.f ? rsqrtf(sum) : 0.f;
}
__global__ void __launch_bounds__(256) k_norm(const int* __restrict__ rp,
                                              const int* __restrict__ col,
                                              float* __restrict__ val,
                                              const float* __restrict__ dinv){
    int node = (blockIdx.x*blockDim.x + threadIdx.x) >> 5;
    int l = threadIdx.x & 31;
    if (node >= NN) return;
    int beg = rp[node], end = rp[node+1];
    float di = -dinv[node];
    for (int e = beg + l; e < end; e += 32)
        val[e] = di * dinv[col[e]] * val[e];
}

// ---------------- prop: fp16 gather input, fp32 accumulate/output (+fp16 mirror) ----------------
__global__ void __launch_bounds__(256) k_prop_h(const int* __restrict__ rp,
                                                const int* __restrict__ col,
                                                const float* __restrict__ val,
                                                const __half* __restrict__ zin_h,
                                                float* __restrict__ zout,
                                                __half* __restrict__ zout_h){
    int node = (blockIdx.x*blockDim.x + threadIdx.x) >> 5;
    int l = threadIdx.x & 31;
    if (node >= NN) return;
    int beg = rp[node], end = rp[node+1];
    const uint2* zh = reinterpret_cast<const uint2*>(zin_h);   // 32 x uint2 per row
    float4 a0 = make_float4(0.f,0.f,0.f,0.f);
    float4 a1 = a0, a2 = a0, a3 = a0;
    int e = beg;
    for (; e + 4 <= end; e += 4){
        int   s0 = __ldg(&col[e  ]), s1 = __ldg(&col[e+1]);
        int   s2 = __ldg(&col[e+2]), s3 = __ldg(&col[e+3]);
        float c0 = __ldg(&val[e  ]), c1 = __ldg(&val[e+1]);
        float c2 = __ldg(&val[e+2]), c3 = __ldg(&val[e+3]);
        uint2 u0 = __ldg(&zh[(size_t)s0*(FF/4) + l]);
        uint2 u1 = __ldg(&zh[(size_t)s1*(FF/4) + l]);
        uint2 u2 = __ldg(&zh[(size_t)s2*(FF/4) + l]);
        uint2 u3 = __ldg(&zh[(size_t)s3*(FF/4) + l]);
        float4 v0 = h4_to_f4(u0);
        float4 v1 = h4_to_f4(u1);
        float4 v2 = h4_to_f4(u2);
        float4 v3 = h4_to_f4(u3);
        a0.x = fmaf(c0,v0.x,a0.x); a0.y = fmaf(c0,v0.y,a0.y);
        a0.z = fmaf(c0,v0.z,a0.z); a0.w = fmaf(c0,v0.w,a0.w);
        a1.x = fmaf(c1,v1.x,a1.x); a1.y = fmaf(c1,v1.y,a1.y);
        a1.z = fmaf(c1,v1.z,a1.z); a1.w = fmaf(c1,v1.w,a1.w);
        a2.x = fmaf(c2,v2.x,a2.x); a2.y = fmaf(c2,v2.y,a2.y);
        a2.z = fmaf(c2,v2.z,a2.z); a2.w = fmaf(c2,v2.w,a2.w);
        a3.x = fmaf(c3,v3.x,a3.x); a3.y = fmaf(c3,v3.y,a3.y);
        a3.z = fmaf(c3,v3.z,a3.z); a3.w = fmaf(c3,v3.w,a3.w);
    }
    for (; e < end; e++){
        int   s0 = __ldg(&col[e]);
        float c0 = __ldg(&val[e]);
        float4 v0 = h4_to_f4(__ldg(&zh[(size_t)s0*(FF/4) + l]));
        a0.x = fmaf(c0,v0.x,a0.x); a0.y = fmaf(c0,v0.y,a0.y);
        a0.z = fmaf(c0,v0.z,a0.z); a0.w = fmaf(c0,v0.w,a0.w);
    }
    float4 acc;
    acc.x = (a0.x+a1.x)+(a2.x+a3.x);
    acc.y = (a0.y+a1.y)+(a2.y+a3.y);
    acc.z = (a0.z+a1.z)+(a2.z+a3.z);
    acc.w = (a0.w+a1.w)+(a2.w+a3.w);
    reinterpret_cast<float4*>(zout)[(size_t)node*(FF/4) + l] = acc;
    if (zout_h)
        reinterpret_cast<uint2*>(zout_h)[(size_t)node*(FF/4) + l] = f4_to_h4(acc);
}

// ---------------- fused cheb GEMM + bias + ELU (optional live-row gather) ----------------
#define MT 64
#define KC 32
#define LDZ 68
__global__ void __launch_bounds__(256) k_gemm_elu(const float* __restrict__ z0,
                                                  const float* __restrict__ z1,
                                                  const float* __restrict__ p2,
                                                  const float* __restrict__ Wm,
                                                  const float* __restrict__ bv,
                                                  float* __restrict__ out,
                                                  const int* __restrict__ live,
                                                  const int* __restrict__ nlivep){
    __shared__ float sZ[KC*LDZ];
    __shared__ float sW[KC*FF];
    int tid = threadIdx.x;
    int row0 = blockIdx.x * MT;
    int nrows = live ? __ldg(nlivep) : NN;
    if (row0 >= nrows) return;
    int cg = tid & 31, rg = tid >> 5;
    float acc[8][4];
    #pragma unroll
    for (int r=0;r<8;r++){ acc[r][0]=0.f; acc[r][1]=0.f; acc[r][2]=0.f; acc[r][3]=0.f; }

    const float4* W4 = reinterpret_cast<const float4*>(Wm);
    for (int ch = 0; ch < 12; ch++){
        int part = ch >> 2;
        int kloc = (ch & 3) * KC;
        const float* zsrc = (part==0) ? z0 : (part==1 ? z1 : p2);
        __syncthreads();
        #pragma unroll
        for (int q=0;q<2;q++){
            int i   = tid + 256*q;
            int row = i >> 3;
            int seg = i & 7;
            int idx = row0 + row;
            int grow = (idx < nrows) ? (live ? __ldg(&live[idx]) : idx) : -1;
            float4 v = make_float4(0.f,0.f,0.f,0.f);
            if (grow >= 0){
                v = *reinterpret_cast<const float4*>(zsrc + (size_t)grow*FF + kloc + seg*4);
                if (part == 2){
                    float4 a = *reinterpret_cast<const float4*>(z0 + (size_t)grow*FF + kloc + seg*4);
                    v.x = 2.f*v.x - a.x; v.y = 2.f*v.y - a.y;
                    v.z = 2.f*v.z - a.z; v.w = 2.f*v.w - a.w;
                }
            }
            int kk = seg*4;
            sZ[(kk+0)*LDZ+row] = v.x; sZ[(kk+1)*LDZ+row] = v.y;
            sZ[(kk+2)*LDZ+row] = v.z; sZ[(kk+3)*LDZ+row] = v.w;
        }
        size_t wbase = (size_t)(part*128 + kloc) * (FF/4);
        #pragma unroll
        for (int q=0;q<4;q++){
            int i = tid + 256*q;
            reinterpret_cast<float4*>(sW)[i] = W4[wbase + i];
        }
        __syncthreads();
        #pragma unroll
        for (int kk=0; kk<KC; kk++){
            float4 w4 = *reinterpret_cast<const float4*>(sW + kk*FF + cg*4);
            const float* zr = sZ + kk*LDZ + rg*8;
            float4 za = *reinterpret_cast<const float4*>(zr);
            float4 zb = *reinterpret_cast<const float4*>(zr+4);
            float zv[8] = {za.x,za.y,za.z,za.w,zb.x,zb.y,zb.z,zb.w};
            #pragma unroll
            for (int r=0;r<8;r++){
                acc[r][0] = fmaf(zv[r], w4.x, acc[r][0]);
                acc[r][1] = fmaf(zv[r], w4.y, acc[r][1]);
                acc[r][2] = fmaf(zv[r], w4.z, acc[r][2]);
                acc[r][3] = fmaf(zv[r], w4.w, acc[r][3]);
            }
        }
    }
    float4 b4 = *reinterpret_cast<const float4*>(bv + cg*4);
    #pragma unroll
    for (int r=0;r<8;r++){
        int idx = row0 + rg*8 + r;
        if (idx < nrows){
            int grow = live ? __ldg(&live[idx]) : idx;
            float4 o;
            o.x = eluf(acc[r][0] + b4.x);
            o.y = eluf(acc[r][1] + b4.y);
            o.z = eluf(acc[r][2] + b4.z);
            o.w = eluf(acc[r][3] + b4.w);
            *reinterpret_cast<float4*>(out + (size_t)grow*FF + cg*4) = o;
        }
    }
}

// ---------------- graclus matching ----------------
__global__ void k_partner(const int* __restrict__ src, const int* __restrict__ dst,
                          int* __restrict__ pt){
    int e = blockIdx.x*blockDim.x + threadIdx.x;
    if (e >= EE) return;
    float c = g_cut[e];
    int s = src[e];
    if (c > NEGINF && c == g_m[s])
        atomicMax(&pt[s], dst[e]);
}
__global__ void k_cluster(const int* __restrict__ pt, int* __restrict__ cl){
    int i = blockIdx.x*blockDim.x + threadIdx.x;
    if (i >= NN) return;
    int p = pt[i];
    int c = i;
    if (p >= 0 && p != i && pt[p] == i) c = min(i, p);
    cl[i] = c;
}
__global__ void k_livelist(const int* __restrict__ pt){
    int i = blockIdx.x*blockDim.x + threadIdx.x;
    if (i >= NN) return;
    int p = pt[i];
    bool dead = (p >= 0 && p != i && pt[p] == i && p < i);
    if (!dead){
        int pos = atomicAdd(&g_nlive[0], 1);
        g_live[pos] = i;
    }
}

// ---------------- pool_x (clusters are pairs); optional fp16 mirror out ----------------
__global__ void k_pool(const int* __restrict__ pt,
                       const float* __restrict__ x, float* __restrict__ xp,
                       __half* __restrict__ xph){
    int t = blockIdx.x*blockDim.x + threadIdx.x;
    int j = t >> 5, l = t & 31;
    if (j >= NN) return;
    int p = pt[j];
    bool mut = (p >= 0 && p != j && pt[p] == j);
    float4 o;
    if (mut && p < j){
        o = make_float4(0.f,0.f,0.f,0.f);
    } else {
        float4 a = reinterpret_cast<const float4*>(x + (size_t)j*FF)[l];
        if (mut){
            float4 b = reinterpret_cast<const float4*>(x + (size_t)p*FF)[l];
            a.x = fmaxf(a.x,b.x); a.y = fmaxf(a.y,b.y);
            a.z = fmaxf(a.z,b.z); a.w = fmaxf(a.w,b.w);
        }
        o = a;
    }
    reinterpret_cast<float4*>(xp + (size_t)j*FF)[l] = o;
    if (xph)
        reinterpret_cast<uint2*>(xph)[(size_t)j*(FF/4) + l] = f4_to_h4(o);
}

// ---------------- pooled edges: relabel + hash dedup ----------------
__global__ void k_pool_edges(const int* __restrict__ src, const int* __restrict__ dst){
    int e = blockIdx.x*blockDim.x + threadIdx.x;
    if (e >= EE) return;
    int s = g_c1[src[e]], d = g_c1[dst[e]];
    g_s2[e] = s; g_d2[e] = d;
    float w = 0.f;
    if (s != d){
        unsigned key = (unsigned)s * (unsigned)NN + (unsigned)d;
        unsigned h = (key * 2654435761u) >> (32 - HBITS);
        h &= HMASK;
        while (true){
            unsigned old = atomicCAS(&g_hash[h], 0xFFFFFFFFu, key);
            if (old == 0xFFFFFFFFu){ w = 1.f; break; }
            if (old == key){ w = 0.f; break; }
            h = (h + 1u) & HMASK;
        }
    }
    g_w2[e] = w;
}

// ---------------- fused log_softmax + gather ----------------
__global__ void k_smax_gather(float* __restrict__ outp){
    int t = blockIdx.x*blockDim.x + threadIdx.x;
    int i = t >> 5, l = t & 31;
    if (i >= NN) return;
    int r = g_c2[g_c1[i]];
    float4 v = reinterpret_cast<const float4*>(g_xp2 + (size_t)r*FF)[l];
    float mx = fmaxf(fmaxf(v.x,v.y), fmaxf(v.z,v.w));
    #pragma unroll
    for (int off=16; off>0; off>>=1) mx = fmaxf(mx, __shfl_xor_sync(0xFFFFFFFFu, mx, off));
    float s = expf(v.x-mx)+expf(v.y-mx)+expf(v.z-mx)+expf(v.w-mx);
    #pragma unroll
    for (int off=16; off>0; off>>=1) s += __shfl_xor_sync(0xFFFFFFFFu, s, off);
    float lse = mx + logf(s);
    v.x -= lse; v.y -= lse; v.z -= lse; v.w -= lse;
    reinterpret_cast<float4*>(outp + (size_t)i*FF)[l] = v;
}

// ---------------- host ----------------
static void* symaddr(const void* s){ void* p = nullptr; cudaGetSymbolAddress(&p, s); return p; }

extern "C" void kernel_launch(void* const* d_in, const int* in_sizes, int n_in,
                              void* d_out, int out_size) {
    const float* x  = (const float*)d_in[0];
    const float* ew = (const float*)d_in[1];
    const float* W1 = (const float*)d_in[2];
    const float* b1 = (const float*)d_in[3];
    const float* W2 = (const float*)d_in[4];
    const float* b2 = (const float*)d_in[5];
    const int*   ei = (const int*)  d_in[6];
    const int* src = ei;
    const int* dst = ei + EE;
    float* outp = (float*)d_out;

    float*  z1   = (float*)  symaddr(g_z1);
    float*  p2   = (float*)  symaddr(g_p2);
    float*  feat = (float*)  symaddr(g_feat);
    float*  xp1  = (float*)  symaddr(g_xp1);
    float*  xp2  = (float*)  symaddr(g_xp2);
    __half* h_in = (__half*) symaddr(g_h_in);
    __half* h_z1 = (__half*) symaddr(g_h_z1);
    int*    cnt1 = (int*)    symaddr(g_cnt1);
    int*    cnt2 = (int*)    symaddr(g_cnt2);
    void*   hash = symaddr(g_hash);
    int*    c1   = (int*)    symaddr(g_c1);
    int*    c2   = (int*)    symaddr(g_c2);
    int*    s2   = (int*)    symaddr(g_s2);
    int*    d2   = (int*)    symaddr(g_d2);
    float*  w2   = (float*)  symaddr(g_w2);
    int*    rp1  = (int*)    symaddr(g_rp1);
    int*    rp2  = (int*)    symaddr(g_rp2);
    int*    col1 = (int*)    symaddr(g_col1);
    int*    col2 = (int*)    symaddr(g_col2);
    float*  val1 = (float*)  symaddr(g_val1);
    float*  val2 = (float*)  symaddr(g_val2);
    float*  di1  = (float*)  symaddr(g_dinv1);
    float*  di2  = (float*)  symaddr(g_dinv2);
    float*  dc1  = (float*)  symaddr(g_dcinv1);
    float*  dc2  = (float*)  symaddr(g_dcinv2);
    int*    pt1  = (int*)    symaddr(g_pt1);
    int*    pt2  = (int*)    symaddr(g_pt2);
    int*    live = (int*)    symaddr(g_live);
    int*    nliv = (int*)    symaddr(g_nlive);

    static cudaStream_t sB = nullptr, sC = nullptr;
    static cudaEvent_t evRoot, evFill, evC1, evB2, evCvt;
    if (!sB){
        cudaStreamCreate(&sB);
        cudaStreamCreate(&sC);
        cudaEventCreateWithFlags(&evRoot, cudaEventDisableTiming);
        cudaEventCreateWithFlags(&evFill, cudaEventDisableTiming);
        cudaEventCreateWithFlags(&evC1,  cudaEventDisableTiming);
        cudaEventCreateWithFlags(&evB2,  cudaEventDisableTiming);
        cudaEventCreateWithFlags(&evCvt, cudaEventDisableTiming);
    }

    const int EB = EE/256;
    const int NB = (NN+255)/256;
    const int PB = (NN*32+255)/256;
    const int GB = (NN+MT-1)/MT;
    const int CB = (NN*FF/4+255)/256;

    // ===== fork point for side streams (required for graph capture) =====
    cudaMemsetAsync(cnt1, 0, NN*sizeof(int));
    cudaEventRecord(evRoot, 0);

    // ===== C: build fp16 mirror of x (hidden under CSR head) =====
    cudaStreamWaitEvent(sC, evRoot, 0);
    k_cvt<<<CB,256,0,sC>>>(x, h_in);
    cudaEventRecord(evCvt, sC);

    // ===== A: block-1 CSR build =====
    k_count<<<EB,256>>>(dst, ew, cnt1);
    k_scan1<<<NB,256>>>(cnt1, dc1, rp1);
    k_scan2<<<1,256>>>();
    k_scan3<<<NB,256>>>(rp1, pt1);
    cudaMemsetAsync(cnt1, 0, NN*sizeof(int));
    k_fill<<<EB,256>>>(src, dst, ew, rp1, cnt1, dc1, col1, val1);
    cudaEventRecord(evFill, 0);

    // ===== B: matching + pooled-graph CSR build (hidden) =====
    cudaStreamWaitEvent(sB, evFill, 0);
    k_partner<<<EB,256,0,sB>>>(src, dst, pt1);
    k_cluster<<<NB,256,0,sB>>>(pt1, c1);
    cudaEventRecord(evC1, sB);
    cudaMemsetAsync(nliv, 0, sizeof(int), sB);
    k_livelist<<<NB,256,0,sB>>>(pt1);
    cudaMemsetAsync(hash, 0xFF, HSIZE*sizeof(unsigned), sB);
    k_pool_edges<<<EB,256,0,sB>>>(src, dst);
    cudaMemsetAsync(cnt2, 0, NN*sizeof(int), sB);
    k_count<<<EB,256,0,sB>>>(d2, w2, cnt2);
    k_scan1<<<NB,256,0,sB>>>(cnt2, dc2, rp2);
    k_scan2<<<1,256,0,sB>>>();
    k_scan3<<<NB,256,0,sB>>>(rp2, pt2);
    cudaMemsetAsync(cnt2, 0, NN*sizeof(int), sB);
    k_fill<<<EB,256,0,sB>>>(s2, d2, w2, rp2, cnt2, dc2, col2, val2);
    k_rowsum<<<PB,256,0,sB>>>(rp2, val2, di2);
    k_norm<<<PB,256,0,sB>>>(rp2, col2, val2, di2);
    k_partner<<<EB,256,0,sB>>>(s2, d2, pt2);
    k_cluster<<<NB,256,0,sB>>>(pt2, c2);
    cudaEventRecord(evB2, sB);

    // ===== A: block-1 heavy chain =====
    k_rowsum<<<PB,256>>>(rp1, val1, di1);
    k_norm<<<PB,256>>>(rp1, col1, val1, di1);
    cudaStreamWaitEvent(0, evCvt, 0);
    k_prop_h<<<PB,256>>>(rp1, col1, val1, h_in, z1, h_z1);
    k_prop_h<<<PB,256>>>(rp1, col1, val1, h_z1, p2, nullptr);
    k_gemm_elu<<<GB,256>>>(x, z1, p2, W1, b1, feat, nullptr, nullptr);
    cudaStreamWaitEvent(0, evC1, 0);
    k_pool<<<PB,256>>>(pt1, feat, xp1, h_in);    // reuse h_in as xp1 mirror

    // ===== A: block-2 heavy chain =====
    cudaStreamWaitEvent(0, evB2, 0);
    k_prop_h<<<PB,256>>>(rp2, col2, val2, h_in, z1, h_z1);
    k_prop_h<<<PB,256>>>(rp2, col2, val2, h_z1, p2, nullptr);
    k_gemm_elu<<<GB,256>>>(xp1, z1, p2, W2, b2, feat, live, nliv);
    k_pool<<<PB,256>>>(pt2, feat, xp2, nullptr);

    // ===== output =====
    k_smax_gather<<<PB,256>>>(outp);
}